// round 7
// baseline (speedup 1.0000x reference)
#include <cuda_runtime.h>
#include <cstdint>

// GCN: out[dst] += w * (data @ theta)[src]
// R3: replace f32 atomics with per-launch CSR build (counting sort by dst)
//     + gather aggregation (zero f32 atomics, one store per output).

#define D 64
#define MAXN 100000
#define MAXE 1200000
#define SCAN_BLK 512
#define SCAN_ELEMS 2048              // 512 threads x 4
#define MAXNB ((MAXN + SCAN_ELEMS - 1) / SCAN_ELEMS + 1)

__device__ float g_proj[(size_t)MAXN * D];        // data @ theta
__device__ int   g_deg[MAXN];                     // histogram
__device__ int   g_partial[MAXN];                 // per-block exclusive scan
__device__ int   g_bsum[MAXNB];                   // block sums
__device__ int   g_rowstart[MAXN + 1];            // CSR row offsets
__device__ int   g_cursor[MAXN];                  // binning cursors
__device__ int2  g_edges[MAXE];                   // dst-sorted (src, w bits)

// ---------------------------------------------------------------------------
__global__ void __launch_bounds__(256) zero_deg_kernel(int* deg, int n) {
    int i = blockIdx.x * blockDim.x + threadIdx.x;
    if (i < n) deg[i] = 0;
}

// ---------------------------------------------------------------------------
__global__ void __launch_bounds__(256) hist_kernel(const int* __restrict__ dst,
                                                   int* __restrict__ deg, int n_edges) {
    int e = blockIdx.x * blockDim.x + threadIdx.x;
    if (e < n_edges) atomicAdd(&deg[dst[e]], 1);
}

// ---------------------------------------------------------------------------
// scan stage A: per-block exclusive scan of deg (2048 elems/block), emit block sums
__global__ void __launch_bounds__(SCAN_BLK) scanA_kernel(const int* __restrict__ deg,
                                                         int* __restrict__ partial,
                                                         int* __restrict__ bsum, int n) {
    __shared__ int s[SCAN_BLK];
    int tid = threadIdx.x;
    int base = blockIdx.x * SCAN_ELEMS + tid * 4;

    int v0 = (base + 0 < n) ? deg[base + 0] : 0;
    int v1 = (base + 1 < n) ? deg[base + 1] : 0;
    int v2 = (base + 2 < n) ? deg[base + 2] : 0;
    int v3 = (base + 3 < n) ? deg[base + 3] : 0;
    int tsum = v0 + v1 + v2 + v3;

    s[tid] = tsum;
    __syncthreads();
    #pragma unroll
    for (int off = 1; off < SCAN_BLK; off <<= 1) {
        int add = (tid >= off) ? s[tid - off] : 0;
        __syncthreads();
        s[tid] += add;
        __syncthreads();
    }
    int excl = s[tid] - tsum;   // exclusive prefix of this thread's 4 elems

    if (base + 0 < n) partial[base + 0] = excl;
    if (base + 1 < n) partial[base + 1] = excl + v0;
    if (base + 2 < n) partial[base + 2] = excl + v0 + v1;
    if (base + 3 < n) partial[base + 3] = excl + v0 + v1 + v2;
    if (tid == SCAN_BLK - 1) bsum[blockIdx.x] = s[tid];
}

// scan stage B: exclusive scan of block sums (single block, serial — tiny)
__global__ void scanB_kernel(int* bsum, int nb) {
    if (threadIdx.x == 0) {
        int run = 0;
        for (int i = 0; i < nb; i++) {
            int v = bsum[i];
            bsum[i] = run;
            run += v;
        }
    }
}

// scan stage C: rowstart[i] = partial[i] + bsum[i>>11]; cursor copy; rowstart[n] = E
__global__ void __launch_bounds__(256) scanC_kernel(const int* __restrict__ partial,
                                                    const int* __restrict__ bsum,
                                                    int* __restrict__ rowstart,
                                                    int* __restrict__ cursor,
                                                    int n, int n_edges) {
    int i = blockIdx.x * blockDim.x + threadIdx.x;
    if (i < n) {
        int v = partial[i] + bsum[i >> 11];
        rowstart[i] = v;
        cursor[i] = v;
    }
    if (i == n) rowstart[n] = n_edges;
}

// ---------------------------------------------------------------------------
// bin edges into dst-sorted order: (src, w bits)
__global__ void __launch_bounds__(256) bin_kernel(const int* __restrict__ src,
                                                  const int* __restrict__ dst,
                                                  const float* __restrict__ w,
                                                  int* __restrict__ cursor,
                                                  int2* __restrict__ edges, int n_edges) {
    int e = blockIdx.x * blockDim.x + threadIdx.x;
    if (e >= n_edges) return;
    int d = dst[e];
    int p = atomicAdd(&cursor[d], 1);
    edges[p] = make_int2(src[e], __float_as_int(w[e]));
}

// ---------------------------------------------------------------------------
// proj = data @ theta   [N,64]x[64,64], 4-row register blocking (theta LDS reused x4)
__global__ void __launch_bounds__(256) proj_kernel(const float* __restrict__ data,
                                                   const float* __restrict__ theta,
                                                   float* __restrict__ proj, int n_rows) {
    __shared__ float s_theta[D * D];
    for (int i = threadIdx.x; i < D * D; i += 256)
        s_theta[i] = theta[i];
    __syncthreads();

    const int col = threadIdx.x & (D - 1);
    const int rg  = threadIdx.x >> 6;          // 0..3
    const int r0  = blockIdx.x * 16 + rg * 4;
    if (r0 >= n_rows) return;

    if (r0 + 3 < n_rows) {
        const float* d0 = data + (size_t)r0 * D;
        float acc0 = 0.f, acc1 = 0.f, acc2 = 0.f, acc3 = 0.f;
        #pragma unroll
        for (int k = 0; k < D; k += 4) {
            float4 a0 = *reinterpret_cast<const float4*>(d0 + 0 * D + k);
            float4 a1 = *reinterpret_cast<const float4*>(d0 + 1 * D + k);
            float4 a2 = *reinterpret_cast<const float4*>(d0 + 2 * D + k);
            float4 a3 = *reinterpret_cast<const float4*>(d0 + 3 * D + k);
            float t0 = s_theta[(k + 0) * D + col];
            float t1 = s_theta[(k + 1) * D + col];
            float t2 = s_theta[(k + 2) * D + col];
            float t3 = s_theta[(k + 3) * D + col];
            acc0 += a0.x * t0 + a0.y * t1 + a0.z * t2 + a0.w * t3;
            acc1 += a1.x * t0 + a1.y * t1 + a1.z * t2 + a1.w * t3;
            acc2 += a2.x * t0 + a2.y * t1 + a2.z * t2 + a2.w * t3;
            acc3 += a3.x * t0 + a3.y * t1 + a3.z * t2 + a3.w * t3;
        }
        proj[(size_t)(r0 + 0) * D + col] = acc0;
        proj[(size_t)(r0 + 1) * D + col] = acc1;
        proj[(size_t)(r0 + 2) * D + col] = acc2;
        proj[(size_t)(r0 + 3) * D + col] = acc3;
    } else {
        for (int r = r0; r < n_rows; r++) {
            const float* drow = data + (size_t)r * D;
            float acc = 0.f;
            #pragma unroll
            for (int k = 0; k < D; k++)
                acc += drow[k] * s_theta[k * D + col];
            proj[(size_t)r * D + col] = acc;
        }
    }
}

// ---------------------------------------------------------------------------
// aggregation: 16 lanes per node, float4 per lane, register accumulate,
// single store per output — no f32 atomics, also covers zero-init.
__global__ void __launch_bounds__(256) agg_kernel(const int* __restrict__ rowstart,
                                                  const int2* __restrict__ edges,
                                                  const float4* __restrict__ proj4,
                                                  float4* __restrict__ out4, int n_nodes) {
    int g = blockIdx.x * 16 + (threadIdx.x >> 4);
    if (g >= n_nodes) return;
    int lane = threadIdx.x & 15;

    int beg = rowstart[g];
    int end = rowstart[g + 1];

    float4 acc = make_float4(0.f, 0.f, 0.f, 0.f);
    int j = beg;
    // 2-way unroll to keep two independent load chains in flight
    for (; j + 1 < end; j += 2) {
        int2 e0 = edges[j];
        int2 e1 = edges[j + 1];
        float4 v0 = proj4[(size_t)e0.x * (D / 4) + lane];
        float4 v1 = proj4[(size_t)e1.x * (D / 4) + lane];
        float w0 = __int_as_float(e0.y);
        float w1 = __int_as_float(e1.y);
        acc.x += w0 * v0.x + w1 * v1.x;
        acc.y += w0 * v0.y + w1 * v1.y;
        acc.z += w0 * v0.z + w1 * v1.z;
        acc.w += w0 * v0.w + w1 * v1.w;
    }
    if (j < end) {
        int2 e0 = edges[j];
        float4 v0 = proj4[(size_t)e0.x * (D / 4) + lane];
        float w0 = __int_as_float(e0.y);
        acc.x += w0 * v0.x;
        acc.y += w0 * v0.y;
        acc.z += w0 * v0.z;
        acc.w += w0 * v0.w;
    }
    out4[(size_t)g * (D / 4) + lane] = acc;
}

// ---------------------------------------------------------------------------
extern "C" void kernel_launch(void* const* d_in, const int* in_sizes, int n_in,
                              void* d_out, int out_size) {
    const int*   src   = (const int*)  d_in[0];
    const int*   dst   = (const int*)  d_in[1];
    const float* w     = (const float*)d_in[2];
    const float* data  = (const float*)d_in[3];
    const float* theta = (const float*)d_in[4];

    const int n_edges = in_sizes[0];
    const int n_nodes = in_sizes[3] / D;

    float* proj;     cudaGetSymbolAddress((void**)&proj, g_proj);
    int*   deg;      cudaGetSymbolAddress((void**)&deg, g_deg);
    int*   partial;  cudaGetSymbolAddress((void**)&partial, g_partial);
    int*   bsum;     cudaGetSymbolAddress((void**)&bsum, g_bsum);
    int*   rowstart; cudaGetSymbolAddress((void**)&rowstart, g_rowstart);
    int*   cursor;   cudaGetSymbolAddress((void**)&cursor, g_cursor);
    int2*  edges;    cudaGetSymbolAddress((void**)&edges, g_edges);

    const int nb = (n_nodes + SCAN_ELEMS - 1) / SCAN_ELEMS;

    // CSR build
    zero_deg_kernel<<<(n_nodes + 255) / 256, 256>>>(deg, n_nodes);
    hist_kernel<<<(n_edges + 255) / 256, 256>>>(dst, deg, n_edges);
    scanA_kernel<<<nb, SCAN_BLK>>>(deg, partial, bsum, n_nodes);
    scanB_kernel<<<1, 32>>>(bsum, nb);
    scanC_kernel<<<(n_nodes + 256) / 256, 256>>>(partial, bsum, rowstart, cursor,
                                                 n_nodes, n_edges);
    bin_kernel<<<(n_edges + 255) / 256, 256>>>(src, dst, w, cursor, edges, n_edges);

    // projection
    proj_kernel<<<(n_nodes + 15) / 16, 256>>>(data, theta, proj, n_nodes);

    // gather aggregation (writes every output exactly once)
    agg_kernel<<<(n_nodes + 15) / 16, 256>>>(rowstart, edges, (const float4*)proj,
                                             (float4*)d_out, n_nodes);
}